// round 2
// baseline (speedup 1.0000x reference)
#include <cuda_runtime.h>
#include <math.h>

// ---------------- problem constants ----------------
#define D_IN  768
#define NH    8
#define HD    96
#define HID   768
#define UP    1536
#define FUSED 2320
#define KER   4
#define CS    64
#define NB    2
#define SEQ   4096
#define TOK   (NB*SEQ)        // 8192 rows
#define NC    (SEQ/CS)        // 64 chunks per sequence
#define NCHUNK (NB*NH*NC)     // 1024

// proj column offsets
#define Q_OFF 16
#define K_OFF 784
#define V_OFF 1552

// ---------------- scratch (device globals; no allocation) ----------------
__device__ float g_xn  [TOK*D_IN];
__device__ float g_xt  [TOK*UP];
__device__ float g_rt  [TOK*HID];
__device__ float g_xc  [TOK*UP];
__device__ float g_skip[TOK*HID];
__device__ float g_proj[TOK*FUSED];
__device__ float g_o   [TOK*HID];
__device__ float g_h   [TOK*HID];
__device__ float g_u   [TOK*HID];
__device__ float g_C   [(size_t)NCHUNK*HD*HD];
__device__ float g_n   [NCHUNK*HD];
__device__ float g_lf  [NCHUNK*CS];
__device__ float g_ig  [NCHUNK*CS];

// ---------------- helpers ----------------
__device__ __forceinline__ float block_sum_256(float v) {
    __shared__ float sh[8];
    int lane = threadIdx.x & 31;
    int w    = threadIdx.x >> 5;
    #pragma unroll
    for (int o = 16; o > 0; o >>= 1) v += __shfl_xor_sync(0xffffffffu, v, o);
    if (lane == 0) sh[w] = v;
    __syncthreads();
    float r = (lane < 8) ? sh[lane] : 0.f;
    #pragma unroll
    for (int o = 16; o > 0; o >>= 1) r += __shfl_xor_sync(0xffffffffu, r, o);
    __syncthreads();   // protect sh for a second call
    return r;
}

__device__ __forceinline__ float sigmoidf_(float x) { return 1.f / (1.f + expf(-x)); }

// ---------------- LayerNorm over 768 (input LN) ----------------
__global__ __launch_bounds__(256) void ln_kernel(const float* __restrict__ x,
                                                 const float* __restrict__ w,
                                                 const float* __restrict__ b,
                                                 float* __restrict__ y)
{
    size_t off = (size_t)blockIdx.x * D_IN;
    int t = threadIdx.x;
    float v0 = x[off + t], v1 = x[off + t + 256], v2 = x[off + t + 512];
    float mean = block_sum_256(v0 + v1 + v2) * (1.f / 768.f);
    float d0 = v0 - mean, d1 = v1 - mean, d2 = v2 - mean;
    float var = block_sum_256(d0*d0 + d1*d1 + d2*d2) * (1.f / 768.f);
    float rstd = rsqrtf(var + 1e-6f);
    y[off + t      ] = d0 * rstd * w[t      ] + b[t      ];
    y[off + t + 256] = d1 * rstd * w[t + 256] + b[t + 256];
    y[off + t + 512] = d2 * rstd * w[t + 512] + b[t + 512];
}

// ---------------- generic SGEMM: C = A[M,K] @ W[K,N] + bias, epilogues ----------------
// epi: 0 = bias, 1 = sigmoid(bias+acc), 2 = bias+acc+resid
__global__ __launch_bounds__(256) void sgemm_kernel(
    const float* __restrict__ A, const float* __restrict__ W,
    const float* __restrict__ bias, const float* __restrict__ resid,
    float* __restrict__ C, int M, int N, int K, int epi)
{
    __shared__ float As[8*128];
    __shared__ float Bs[8*128];
    int bm = blockIdx.y * 128;
    int bn = blockIdx.x * 128;
    int tid = threadIdx.x;
    int tx = tid & 15;       // n dir
    int ty = tid >> 4;       // m dir
    float acc[8][8];
    #pragma unroll
    for (int i = 0; i < 8; i++)
        #pragma unroll
        for (int j = 0; j < 8; j++) acc[i][j] = 0.f;

    int arow = tid >> 1;
    int acol = (tid & 1) << 2;
    int brow = tid >> 5;
    int bcol = (tid & 31) << 2;

    for (int k0 = 0; k0 < K; k0 += 8) {
        float4 av = *reinterpret_cast<const float4*>(A + (size_t)(bm + arow) * K + (k0 + acol));
        As[(acol+0)*128 + arow] = av.x;
        As[(acol+1)*128 + arow] = av.y;
        As[(acol+2)*128 + arow] = av.z;
        As[(acol+3)*128 + arow] = av.w;
        int gn = bn + bcol;
        float4 bv;
        if (gn + 3 < N) {
            bv = *reinterpret_cast<const float4*>(W + (size_t)(k0 + brow) * N + gn);
        } else {
            bv.x = (gn+0 < N) ? W[(size_t)(k0+brow)*N + gn+0] : 0.f;
            bv.y = (gn+1 < N) ? W[(size_t)(k0+brow)*N + gn+1] : 0.f;
            bv.z = (gn+2 < N) ? W[(size_t)(k0+brow)*N + gn+2] : 0.f;
            bv.w = 0.f;
        }
        Bs[brow*128 + bcol+0] = bv.x;
        Bs[brow*128 + bcol+1] = bv.y;
        Bs[brow*128 + bcol+2] = bv.z;
        Bs[brow*128 + bcol+3] = bv.w;
        __syncthreads();
        #pragma unroll
        for (int kk = 0; kk < 8; kk++) {
            float4 a0 = *reinterpret_cast<const float4*>(&As[kk*128 + ty*8]);
            float4 a1 = *reinterpret_cast<const float4*>(&As[kk*128 + ty*8 + 4]);
            float4 b0 = *reinterpret_cast<const float4*>(&Bs[kk*128 + tx*8]);
            float4 b1 = *reinterpret_cast<const float4*>(&Bs[kk*128 + tx*8 + 4]);
            float a[8]  = {a0.x,a0.y,a0.z,a0.w,a1.x,a1.y,a1.z,a1.w};
            float bb[8] = {b0.x,b0.y,b0.z,b0.w,b1.x,b1.y,b1.z,b1.w};
            #pragma unroll
            for (int i = 0; i < 8; i++)
                #pragma unroll
                for (int j = 0; j < 8; j++)
                    acc[i][j] = fmaf(a[i], bb[j], acc[i][j]);
        }
        __syncthreads();
    }
    #pragma unroll
    for (int i = 0; i < 8; i++) {
        size_t m = (size_t)bm + ty*8 + i;
        #pragma unroll
        for (int j = 0; j < 8; j++) {
            int n = bn + tx*8 + j;
            if (n < N) {
                float v = acc[i][j] + bias[n];
                if (epi == 1)      v = sigmoidf_(v);
                else if (epi == 2) v += resid[m*(size_t)N + n];
                C[m*(size_t)N + n] = v;
            }
        }
    }
}

// ---------------- causal conv (K=4, shared scalar kernel) + SiLU ----------------
__global__ __launch_bounds__(256) void conv_kernel(const float* __restrict__ cw,
                                                   const float* __restrict__ cb)
{
    size_t idx = (size_t)blockIdx.x * 256 + threadIdx.x;   // over TOK*UP
    int c  = (int)(idx % UP);
    int sr = (int)(idx / UP);   // b*SEQ + s
    int s  = sr & (SEQ - 1);
    float acc = cb[0];
    #pragma unroll
    for (int j = 0; j < KER; j++) {
        int sp = s - (KER - 1) + j;
        if (sp >= 0) acc = fmaf(cw[j], g_xt[(size_t)(sr - (KER - 1) + j) * UP + c], acc);
    }
    g_xc[idx] = acc * sigmoidf_(acc);   // SiLU
}

// ---------------- phase A: per-chunk gates + C/n contributions ----------------
__global__ __launch_bounds__(256) void chunk_state_kernel()
{
    extern __shared__ float sm[];
    float* ks  = sm;               // CS*HD
    float* vs  = ks + CS*HD;       // CS*HD
    float* wc  = vs + CS*HD;       // 64
    float* lfs = wc + 64;          // 64
    float* igs = lfs + 64;         // 64
    float* lgs = igs + 64;         // 64

    int chunk = blockIdx.x;
    int c  = chunk & 63;
    int bh = chunk >> 6;
    int h  = bh & 7;
    int b  = bh >> 3;
    int tid = threadIdx.x;
    size_t row0 = (size_t)(b*SEQ + c*CS) * FUSED;

    if (tid < CS) {
        const float* pr = g_proj + row0 + (size_t)tid * FUSED;
        float ip = 15.f * tanhf(pr[h]      * (1.f/15.f));
        float fp = 15.f * tanhf(pr[NH + h] * (1.f/15.f));
        float mx = fmaxf(ip, fp);
        igs[tid] = expf(ip - mx);
        lgs[tid] = logf(expf(fp - mx) + 1e-8f);
    }
    __syncthreads();
    if (tid == 0) {
        float run = 0.f;
        for (int l = 0; l < CS; l++) { run += lgs[l]; lfs[l] = run; }
    }
    __syncthreads();
    if (tid < CS) wc[tid] = expf(lfs[tid] - lfs[CS-1]) * igs[tid];

    const float rs = 1.f / sqrtf((float)HD);
    for (int idx = tid; idx < CS*HD; idx += 256) {
        int l = idx / HD, d = idx % HD;
        const float* pr = g_proj + row0 + (size_t)l * FUSED;
        int col = h * HD + d;
        ks[idx] = pr[K_OFF + col] * rs;
        vs[idx] = pr[V_OFF + col];
    }
    __syncthreads();

    float* Co = g_C + (size_t)chunk * (HD*HD);
    for (int idx = tid; idx < HD*HD; idx += 256) {
        int d = idx / HD, e = idx - d*HD;
        float acc = 0.f;
        #pragma unroll 16
        for (int l = 0; l < CS; l++) acc = fmaf(wc[l] * vs[l*HD + d], ks[l*HD + e], acc);
        Co[idx] = acc;
    }
    if (tid < HD) {
        float acc = 0.f;
        for (int l = 0; l < CS; l++) acc = fmaf(wc[l], ks[l*HD + tid], acc);
        g_n[(size_t)chunk*HD + tid] = acc;
    }
    if (tid < CS) { g_lf[chunk*CS + tid] = lfs[tid]; g_ig[chunk*CS + tid] = igs[tid]; }
}

// ---------------- phase B: exclusive scan over chunks (final forget == 1) ----------------
__global__ __launch_bounds__(256) void chunk_scan_kernel()
{
    int bh = blockIdx.x;     // 0..15
    int tid = threadIdx.x;
    for (int e = tid; e < HD*HD; e += 256) {
        float run = 0.f;
        for (int c = 0; c < NC; c++) {
            size_t idx = ((size_t)(bh*NC + c)) * (HD*HD) + e;
            float t = g_C[idx]; g_C[idx] = run; run += t;
        }
    }
    for (int e = tid; e < HD; e += 256) {
        float run = 0.f;
        for (int c = 0; c < NC; c++) {
            size_t idx = ((size_t)(bh*NC + c)) * HD + e;
            float t = g_n[idx]; g_n[idx] = run; run += t;
        }
    }
}

// ---------------- phase C: intra-chunk attention + state readout ----------------
__global__ __launch_bounds__(256) void chunk_out_kernel()
{
    extern __shared__ float sm[];
    float* qs   = sm;              // 6144
    float* ks   = qs  + CS*HD;     // 6144
    float* vs   = ks  + CS*HD;     // 6144
    float* Cs   = vs  + CS*HD;     // 9216
    float* Ss   = Cs  + HD*HD;     // 4096   (scores -> attn*w)
    float* Ws   = Ss  + CS*CS;     // 4096   (w)
    float* lfs  = Ws  + CS*CS;     // 64
    float* igs  = lfs + CS;        // 64
    float* nin  = igs + CS;        // 96
    float* dprt = nin + HD;        // 256

    int chunk = blockIdx.x;
    int c  = chunk & 63;
    int bh = chunk >> 6;
    int h  = bh & 7;
    int b  = bh >> 3;
    int tid = threadIdx.x;
    size_t row0 = (size_t)(b*SEQ + c*CS) * FUSED;
    const float rs = 1.f / sqrtf((float)HD);

    for (int idx = tid; idx < CS*HD; idx += 256) {
        int l = idx / HD, d = idx % HD;
        const float* pr = g_proj + row0 + (size_t)l * FUSED;
        int col = h * HD + d;
        qs[idx] = pr[Q_OFF + col];
        ks[idx] = pr[K_OFF + col] * rs;
        vs[idx] = pr[V_OFF + col];
    }
    for (int idx = tid; idx < HD*HD; idx += 256) Cs[idx] = g_C[(size_t)chunk*(HD*HD) + idx];
    if (tid < CS) { lfs[tid] = g_lf[chunk*CS + tid]; igs[tid] = g_ig[chunk*CS + tid]; }
    if (tid < HD) nin[tid] = g_n[(size_t)chunk*HD + tid];
    __syncthreads();

    // scores = q . k
    for (int idx = tid; idx < CS*CS; idx += 256) {
        int i = idx >> 6, j = idx & 63;
        const float* qi = qs + i*HD;
        const float* kj = ks + j*HD;
        float acc = 0.f;
        #pragma unroll 16
        for (int d = 0; d < HD; d++) acc = fmaf(qi[d], kj[d], acc);
        Ss[idx] = acc;
    }
    __syncthreads();

    // masked (j<i) softmax + decay weights
    if (tid < CS) {
        int i = tid;
        float m = -1e30f;
        for (int j = 0; j < i; j++) m = fmaxf(m, Ss[i*CS + j]);
        float ssum = 0.f;
        for (int j = 0; j < i; j++) { float p = expf(Ss[i*CS + j] - m); Ss[i*CS + j] = p; ssum += p; }
        float inv = (i > 0) ? 1.f / ssum : 0.f;
        float lfi = lfs[i];
        for (int j = 0; j < CS; j++) {
            if (j < i) {
                float wv = igs[j] * expf(lfi - lfs[j]);
                Ws[i*CS + j] = wv;
                Ss[i*CS + j] = Ss[i*CS + j] * inv * wv;
            } else {
                Ws[i*CS + j] = 0.f;
                Ss[i*CS + j] = 0.f;
            }
        }
    }
    __syncthreads();

    // outputs: 4 threads per row i, 24 d's each
    {
        int i = tid >> 2, part = tid & 3;
        float hacc[24];
        float nq = 0.f;
        const float* qrow = qs + i*HD;
        const float* aw = Ss + i*CS;
        const float* wr = Ws + i*CS;
        #pragma unroll 4
        for (int dd = 0; dd < 24; dd++) {
            int d = part*24 + dd;
            float hi = 0.f, ni = 0.f;
            #pragma unroll 8
            for (int j = 0; j < CS; j++) {
                hi = fmaf(aw[j], vs[j*HD + d], hi);
                ni = fmaf(wr[j], ks[j*HD + d], ni);
            }
            float h0 = 0.f;
            const float* crow = Cs + d*HD;
            #pragma unroll 8
            for (int e = 0; e < HD; e++) h0 = fmaf(crow[e], qrow[e], h0);
            hacc[dd] = h0 + hi;
            nq = fmaf(ni + nin[d], qrow[d], nq);
        }
        dprt[tid] = nq;
        __syncthreads();
        float denom = fmaxf(dprt[i*4+0] + dprt[i*4+1] + dprt[i*4+2] + dprt[i*4+3], 1.f);
        float invd = 1.f / denom;
        size_t orow = (size_t)(b*SEQ + c*CS + i) * HID + h*HD + part*24;
        for (int dd = 0; dd < 24; dd++) g_h[orow + dd] = hacc[dd] * invd;
    }
}

// ---------------- fused epilogue: u = (LN(o*h)+skip)*silu(r_t) ----------------
__global__ __launch_bounds__(256) void post_kernel(const float* __restrict__ lw,
                                                   const float* __restrict__ lb)
{
    size_t off = (size_t)blockIdx.x * HID;
    int t = threadIdx.x;
    float v0 = g_o[off+t      ] * g_h[off+t      ];
    float v1 = g_o[off+t + 256] * g_h[off+t + 256];
    float v2 = g_o[off+t + 512] * g_h[off+t + 512];
    float mean = block_sum_256(v0 + v1 + v2) * (1.f / 768.f);
    float d0 = v0 - mean, d1 = v1 - mean, d2 = v2 - mean;
    float var = block_sum_256(d0*d0 + d1*d1 + d2*d2) * (1.f / 768.f);
    float rstd = rsqrtf(var + 1e-6f);
    {
        int cx = t;
        float y = d0 * rstd * lw[cx] + lb[cx] + g_skip[off + cx];
        float r = g_rt[off + cx];
        g_u[off + cx] = y * (r * sigmoidf_(r));
    }
    {
        int cx = t + 256;
        float y = d1 * rstd * lw[cx] + lb[cx] + g_skip[off + cx];
        float r = g_rt[off + cx];
        g_u[off + cx] = y * (r * sigmoidf_(r));
    }
    {
        int cx = t + 512;
        float y = d2 * rstd * lw[cx] + lb[cx] + g_skip[off + cx];
        float r = g_rt[off + cx];
        g_u[off + cx] = y * (r * sigmoidf_(r));
    }
}

// ---------------- launch ----------------
extern "C" void kernel_launch(void* const* d_in, const int* in_sizes, int n_in,
                              void* d_out, int out_size)
{
    (void)in_sizes; (void)n_in; (void)out_size;
    const float* x        = (const float*)d_in[0];
    const float* ln_in_w  = (const float*)d_in[1];
    const float* ln_in_b  = (const float*)d_in[2];
    const float* ln_hid_w = (const float*)d_in[3];
    const float* ln_hid_b = (const float*)d_in[4];
    const float* up_l_w   = (const float*)d_in[5];
    const float* up_l_b   = (const float*)d_in[6];
    const float* up_r_w   = (const float*)d_in[7];
    const float* up_r_b   = (const float*)d_in[8];
    const float* down_w   = (const float*)d_in[9];
    const float* down_b   = (const float*)d_in[10];
    const float* conv_w   = (const float*)d_in[11];
    const float* conv_b   = (const float*)d_in[12];
    const float* skip_w   = (const float*)d_in[13];
    const float* skip_b   = (const float*)d_in[14];
    const float* fused_w  = (const float*)d_in[15];
    const float* fused_b  = (const float*)d_in[16];
    const float* wo_w     = (const float*)d_in[17];
    const float* wo_b     = (const float*)d_in[18];
    float* out = (float*)d_out;

    float *p_xn, *p_xt, *p_rt, *p_xc, *p_skip, *p_proj, *p_o, *p_u;
    cudaGetSymbolAddress((void**)&p_xn,   g_xn);
    cudaGetSymbolAddress((void**)&p_xt,   g_xt);
    cudaGetSymbolAddress((void**)&p_rt,   g_rt);
    cudaGetSymbolAddress((void**)&p_xc,   g_xc);
    cudaGetSymbolAddress((void**)&p_skip, g_skip);
    cudaGetSymbolAddress((void**)&p_proj, g_proj);
    cudaGetSymbolAddress((void**)&p_o,    g_o);
    cudaGetSymbolAddress((void**)&p_u,    g_u);

    const int SMEM_A = (2*CS*HD + 4*64) * 4;                                   // 50176 B
    const int SMEM_C = (3*CS*HD + HD*HD + 2*CS*CS + 2*CS + HD + 256) * 4;      // 145280 B
    cudaFuncSetAttribute(chunk_state_kernel, cudaFuncAttributeMaxDynamicSharedMemorySize, SMEM_A);
    cudaFuncSetAttribute(chunk_out_kernel,   cudaFuncAttributeMaxDynamicSharedMemorySize, SMEM_C);

    // 1) input LN
    ln_kernel<<<TOK, 256>>>(x, ln_in_w, ln_in_b, p_xn);
    // 2) x_t = xn @ up_l
    sgemm_kernel<<<dim3(UP/128, TOK/128), 256>>>(p_xn, up_l_w, up_l_b, nullptr, p_xt, TOK, UP, D_IN, 0);
    // 3) r_t = xn @ up_r
    sgemm_kernel<<<dim3(HID/128, TOK/128), 256>>>(p_xn, up_r_w, up_r_b, nullptr, p_rt, TOK, HID, D_IN, 0);
    // 4) causal conv + silu
    conv_kernel<<<(TOK*UP)/256, 256>>>(conv_w, conv_b);
    // 5) x_skip = xc @ skip_w
    sgemm_kernel<<<dim3(HID/128, TOK/128), 256>>>(p_xc, skip_w, skip_b, nullptr, p_skip, TOK, HID, UP, 0);
    // 6) proj = xc @ fused_w
    sgemm_kernel<<<dim3((FUSED+127)/128, TOK/128), 256>>>(p_xc, fused_w, fused_b, nullptr, p_proj, TOK, FUSED, UP, 0);
    // 7) o = sigmoid(xt @ wo_w)
    sgemm_kernel<<<dim3(HID/128, TOK/128), 256>>>(p_xt, wo_w, wo_b, nullptr, p_o, TOK, HID, UP, 1);
    // 8-10) chunked mLSTM attention
    chunk_state_kernel<<<NCHUNK, 256, SMEM_A>>>();
    chunk_scan_kernel<<<NB*NH, 256>>>();
    chunk_out_kernel<<<NCHUNK, 256, SMEM_C>>>();
    // 11) u = (LN(o*h)+skip)*silu(r_t)
    post_kernel<<<TOK, 256>>>(ln_hid_w, ln_hid_b);
    // 12) out = u @ down_w + down_b + x
    sgemm_kernel<<<dim3(HID/128, TOK/128), 256>>>(p_u, down_w, down_b, x, out, TOK, D_IN, HID, 2);
}

// round 14
// speedup vs baseline: 1.1872x; 1.1872x over previous
#include <cuda_runtime.h>
#include <cuda_bf16.h>
#include <math.h>
#include <stdint.h>

// ---------------- problem constants ----------------
#define D_IN  768
#define NH    8
#define HD    96
#define HID   768
#define UP    1536
#define FUSED 2320
#define KER   4
#define CS    64
#define NB    2
#define SEQ   4096
#define TOK   (NB*SEQ)         // 8192 rows
#define NC    (SEQ/CS)         // 64 chunks per sequence
#define NCHUNK (NB*NH*NC)      // 1024

// proj column offsets
#define Q_OFF 16
#define K_OFF 784
#define V_OFF 1552

// ---------------- scratch (device globals; no allocation) ----------------
__device__ float g_xn  [TOK*D_IN];      // fp32 (up_l sgemm input)
__device__ float g_xt  [TOK*UP];        // fp32 (conv input)
__device__ float g_xc  [TOK*UP];        // fp32 (proj sgemm input)
__device__ float g_rt  [TOK*HID];
__device__ float g_skip[TOK*HID];
__device__ float g_proj[TOK*FUSED];
__device__ float g_o   [TOK*HID];
__device__ float g_h   [TOK*HID];
__device__ float g_C   [(size_t)NCHUNK*HD*HD];
__device__ float g_n   [NCHUNK*HD];
__device__ float g_lf  [NCHUNK*CS];
__device__ float g_ig  [NCHUNK*CS];

// 2-level split bf16 activations [row][k]
__device__ __nv_bfloat16 g_xn_h[TOK*D_IN], g_xn_l[TOK*D_IN];
__device__ __nv_bfloat16 g_xt_h[TOK*UP],   g_xt_l[TOK*UP];
__device__ __nv_bfloat16 g_xc_h[TOK*UP],   g_xc_l[TOK*UP];
__device__ __nv_bfloat16 g_u_h [TOK*HID],  g_u_l [TOK*HID];

// 2-level split transposed weights: Wt[n][k]
__device__ __nv_bfloat16 g_wur_h[HID*D_IN],  g_wur_l[HID*D_IN];
__device__ __nv_bfloat16 g_wsk_h[HID*UP],    g_wsk_l[HID*UP];
__device__ __nv_bfloat16 g_wwo_h[HID*UP],    g_wwo_l[HID*UP];
__device__ __nv_bfloat16 g_wdn_h[D_IN*HID],  g_wdn_l[D_IN*HID];

// ---------------- small helpers ----------------
__device__ __forceinline__ uint32_t smem_u32(const void* p) {
    uint32_t a;
    asm("{ .reg .u64 t; cvta.to.shared.u64 t, %1; cvt.u32.u64 %0, t; }" : "=r"(a) : "l"(p));
    return a;
}
#define LDMX4(r, addr) \
    asm volatile("ldmatrix.sync.aligned.m8n8.x4.shared.b16 {%0,%1,%2,%3}, [%4];" \
        : "=r"((r)[0]), "=r"((r)[1]), "=r"((r)[2]), "=r"((r)[3]) : "r"(addr))
#define MMA_BF16(d, a, b) \
    asm volatile("mma.sync.aligned.m16n8k16.row.col.f32.bf16.bf16.f32 " \
        "{%0,%1,%2,%3}, {%4,%5,%6,%7}, {%8,%9}, {%0,%1,%2,%3};" \
        : "+f"((d)[0]), "+f"((d)[1]), "+f"((d)[2]), "+f"((d)[3]) \
        : "r"((a)[0]), "r"((a)[1]), "r"((a)[2]), "r"((a)[3]), "r"((b)[0]), "r"((b)[1]))

__device__ __forceinline__ float sigmoidf_(float x) { return 1.f / (1.f + expf(-x)); }

__device__ __forceinline__ void split2(float v, __nv_bfloat16& h, __nv_bfloat16& l) {
    h = __float2bfloat16(v);
    l = __float2bfloat16(v - __bfloat162float(h));
}

__device__ __forceinline__ float block_sum_256(float v) {
    __shared__ float sh[8];
    int lane = threadIdx.x & 31;
    int w    = threadIdx.x >> 5;
    #pragma unroll
    for (int o = 16; o > 0; o >>= 1) v += __shfl_xor_sync(0xffffffffu, v, o);
    if (lane == 0) sh[w] = v;
    __syncthreads();
    float r = (lane < 8) ? sh[lane] : 0.f;
    #pragma unroll
    for (int o = 16; o > 0; o >>= 1) r += __shfl_xor_sync(0xffffffffu, r, o);
    __syncthreads();
    return r;
}

// ---------------- weight transpose + bf16 hi/lo split ----------------
__global__ __launch_bounds__(256) void wsplit_kernel(const float* __restrict__ W,
                                                     __nv_bfloat16* __restrict__ hi,
                                                     __nv_bfloat16* __restrict__ lo,
                                                     int K, int N)
{
    size_t idx = (size_t)blockIdx.x * 256 + threadIdx.x;   // over N*K
    int n = (int)(idx / K);
    int k = (int)(idx - (size_t)n * K);
    float v = (n < N) ? W[(size_t)k * N + n] : 0.f;
    __nv_bfloat16 h, l;
    split2(v, h, l);
    hi[idx] = h; lo[idx] = l;
}

// ---------------- R2-proven fp32 SIMT SGEMM (+ optional split output) ----------------
// epi: 0 = bias, 1 = sigmoid(bias+acc), 2 = bias+acc+resid
__global__ __launch_bounds__(256) void sgemm_kernel(
    const float* __restrict__ A, const float* __restrict__ W,
    const float* __restrict__ bias, const float* __restrict__ resid,
    float* __restrict__ C, __nv_bfloat16* __restrict__ Ch, __nv_bfloat16* __restrict__ Cl,
    int M, int N, int K, int epi)
{
    __shared__ float As[8*128];
    __shared__ float Bs[8*128];
    int bm = blockIdx.y * 128;
    int bn = blockIdx.x * 128;
    int tid = threadIdx.x;
    int tx = tid & 15;       // n dir
    int ty = tid >> 4;       // m dir
    float acc[8][8];
    #pragma unroll
    for (int i = 0; i < 8; i++)
        #pragma unroll
        for (int j = 0; j < 8; j++) acc[i][j] = 0.f;

    int arow = tid >> 1;
    int acol = (tid & 1) << 2;
    int brow = tid >> 5;
    int bcol = (tid & 31) << 2;

    for (int k0 = 0; k0 < K; k0 += 8) {
        float4 av = *reinterpret_cast<const float4*>(A + (size_t)(bm + arow) * K + (k0 + acol));
        As[(acol+0)*128 + arow] = av.x;
        As[(acol+1)*128 + arow] = av.y;
        As[(acol+2)*128 + arow] = av.z;
        As[(acol+3)*128 + arow] = av.w;
        int gn = bn + bcol;
        float4 bv;
        if (gn + 3 < N) {
            bv = *reinterpret_cast<const float4*>(W + (size_t)(k0 + brow) * N + gn);
        } else {
            bv.x = (gn+0 < N) ? W[(size_t)(k0+brow)*N + gn+0] : 0.f;
            bv.y = (gn+1 < N) ? W[(size_t)(k0+brow)*N + gn+1] : 0.f;
            bv.z = (gn+2 < N) ? W[(size_t)(k0+brow)*N + gn+2] : 0.f;
            bv.w = 0.f;
        }
        Bs[brow*128 + bcol+0] = bv.x;
        Bs[brow*128 + bcol+1] = bv.y;
        Bs[brow*128 + bcol+2] = bv.z;
        Bs[brow*128 + bcol+3] = bv.w;
        __syncthreads();
        #pragma unroll
        for (int kk = 0; kk < 8; kk++) {
            float4 a0 = *reinterpret_cast<const float4*>(&As[kk*128 + ty*8]);
            float4 a1 = *reinterpret_cast<const float4*>(&As[kk*128 + ty*8 + 4]);
            float4 b0 = *reinterpret_cast<const float4*>(&Bs[kk*128 + tx*8]);
            float4 b1 = *reinterpret_cast<const float4*>(&Bs[kk*128 + tx*8 + 4]);
            float a[8]  = {a0.x,a0.y,a0.z,a0.w,a1.x,a1.y,a1.z,a1.w};
            float bb[8] = {b0.x,b0.y,b0.z,b0.w,b1.x,b1.y,b1.z,b1.w};
            #pragma unroll
            for (int i = 0; i < 8; i++)
                #pragma unroll
                for (int j = 0; j < 8; j++)
                    acc[i][j] = fmaf(a[i], bb[j], acc[i][j]);
        }
        __syncthreads();
    }
    #pragma unroll
    for (int i = 0; i < 8; i++) {
        size_t m = (size_t)bm + ty*8 + i;
        #pragma unroll
        for (int j = 0; j < 8; j++) {
            int n = bn + tx*8 + j;
            if (n < N) {
                float v = acc[i][j] + bias[n];
                if (epi == 1)      v = sigmoidf_(v);
                else if (epi == 2) v += resid[m*(size_t)N + n];
                C[m*(size_t)N + n] = v;
                if (Ch) {
                    __nv_bfloat16 h, l;
                    split2(v, h, l);
                    Ch[m*(size_t)N + n] = h;
                    Cl[m*(size_t)N + n] = l;
                }
            }
        }
    }
}

// ---------------- fresh, simple mma GEMM: C = A @ Wt^T, 2-level hi/lo (3-MMA) ----------------
// Single-buffered, synchronous loads, padded smem (no swizzle, no cp.async, no pipeline).
// Smem row: 8 chunks of 16B (0-3 hi k0..31, 4-7 lo), stride 208B (13*16) for conflict-free ldmatrix.
#define G2_STRIDE 208
#define G2_TILE   (128*G2_STRIDE)     // 26624 B
#define G2_SMEM   (2*G2_TILE)         // 53248 B
__global__ __launch_bounds__(256, 2) void gemm2_kernel(
    const __nv_bfloat16* __restrict__ Ah, const __nv_bfloat16* __restrict__ Al,
    const __nv_bfloat16* __restrict__ Bh, const __nv_bfloat16* __restrict__ Bl,
    const float* __restrict__ bias, const float* __restrict__ resid,
    float* __restrict__ C, int M, int N, int K, int epi)
{
    extern __shared__ char smem[];
    const uint32_t sA = smem_u32(smem);
    const uint32_t sB = sA + G2_TILE;
    const int tid  = threadIdx.x;
    const int lane = tid & 31;
    const int warp = tid >> 5;
    const int bm = blockIdx.y * 128;
    const int bn = blockIdx.x * 128;
    const int wm = (warp >> 1) * 32;   // 4 warps along M
    const int wn = (warp & 1) * 64;    // 2 warps along N

    float acc[2][8][4];
    #pragma unroll
    for (int i = 0; i < 2; ++i)
        #pragma unroll
        for (int j = 0; j < 8; ++j)
            #pragma unroll
            for (int q = 0; q < 4; ++q) acc[i][j][q] = 0.f;

    const int nk = K >> 5;
    const int r  = tid >> 1;           // row 0..127
    const int cb = (tid & 1) * 4;      // even thread: hi chunks 0-3; odd: lo chunks 4-7

    for (int ks = 0; ks < nk; ++ks) {
        const int k0 = ks * 32;
        __syncthreads();               // protect smem from previous iteration's ldmatrix
        {
            const __nv_bfloat16* asrc = (tid & 1) ? Al : Ah;
            const __nv_bfloat16* bsrc = (tid & 1) ? Bl : Bh;
            const __nv_bfloat16* ap = asrc + (size_t)(bm + r) * K + k0;
            const __nv_bfloat16* bp = bsrc + (size_t)(bn + r) * K + k0;
            char* rowA = smem + r * G2_STRIDE;
            char* rowB = smem + G2_TILE + r * G2_STRIDE;
            #pragma unroll
            for (int j = 0; j < 4; ++j) {
                *reinterpret_cast<uint4*>(rowA + (cb + j) * 16) =
                    *reinterpret_cast<const uint4*>(ap + j * 8);
                *reinterpret_cast<uint4*>(rowB + (cb + j) * 16) =
                    *reinterpret_cast<const uint4*>(bp + j * 8);
            }
        }
        __syncthreads();

        #pragma unroll
        for (int sub = 0; sub < 2; ++sub) {        // two k16 halves of the k32 slab
            uint32_t ahf[2][4], alf[2][4];
            {
                int rit  = ((lane >> 3) & 1) * 8 + (lane & 7);
                int csel = lane >> 4;
                int ch   = sub * 2 + csel;          // hi chunk 0..3
                #pragma unroll
                for (int mt = 0; mt < 2; ++mt) {
                    int rr = wm + mt * 16 + rit;
                    LDMX4(ahf[mt], sA + rr * G2_STRIDE + ch * 16);
                    LDMX4(alf[mt], sA + rr * G2_STRIDE + (ch + 4) * 16);
                }
            }
            #pragma unroll
            for (int half = 0; half < 2; ++half) {
                uint32_t bhf[4][2], blf[4][2];
                int rb  = (lane & 7) + ((lane >> 4) & 1) * 8;
                int cbb = sub * 2 + ((lane >> 3) & 1);
                #pragma unroll
                for (int np = 0; np < 2; ++np) {
                    int rr = wn + half * 32 + np * 16 + rb;
                    uint32_t t4[4];
                    LDMX4(t4, sB + rr * G2_STRIDE + cbb * 16);
                    bhf[np*2][0]   = t4[0]; bhf[np*2][1]   = t4[1];
                    bhf[np*2+1][0] = t4[2]; bhf[np*2+1][1] = t4[3];
                    LDMX4(t4, sB + rr * G2_STRIDE + (cbb + 4) * 16);
                    blf[np*2][0]   = t4[0]; blf[np*2][1]   = t4[1];
                    blf[np*2+1][0] = t4[2]; blf[np*2+1][1] = t4[3];
                }
                #pragma unroll
                for (int mt = 0; mt < 2; ++mt)
                    #pragma unroll
                    for (int nt = 0; nt < 4; ++nt) {
                        float* d = acc[mt][half*4+nt];
                        MMA_BF16(d, ahf[mt], bhf[nt]);   // h*h
                        MMA_BF16(d, ahf[mt], blf[nt]);   // h*l
                        MMA_BF16(d, alf[mt], bhf[nt]);   // l*h
                    }
            }
        }
    }

    // ---- epilogue ----
    int cr = lane >> 2;
    int cc = (lane & 3) * 2;
    #pragma unroll
    for (int mt = 0; mt < 2; ++mt) {
        #pragma unroll
        for (int rr = 0; rr < 2; ++rr) {
            size_t rg = (size_t)(bm + wm + mt * 16 + rr * 8 + cr);
            #pragma unroll
            for (int nt = 0; nt < 8; ++nt) {
                int n = bn + wn + nt * 8 + cc;
                if (n < N) {
                    float v0 = acc[mt][nt][rr*2+0] + bias[n];
                    float v1 = acc[mt][nt][rr*2+1] + bias[n+1];
                    if (epi == 1) { v0 = sigmoidf_(v0); v1 = sigmoidf_(v1); }
                    else if (epi == 2) { v0 += resid[rg*N+n]; v1 += resid[rg*N+n+1]; }
                    C[rg*N+n]   = v0;
                    C[rg*N+n+1] = v1;
                }
            }
        }
    }
}

// ---------------- LayerNorm over 768 -> fp32 + hi/lo split ----------------
__global__ __launch_bounds__(256) void ln_split_kernel(const float* __restrict__ x,
                                                       const float* __restrict__ w,
                                                       const float* __restrict__ b,
                                                       float* __restrict__ y,
                                                       __nv_bfloat16* __restrict__ yh,
                                                       __nv_bfloat16* __restrict__ yl)
{
    size_t off = (size_t)blockIdx.x * D_IN;
    int t = threadIdx.x;
    float v0 = x[off + t], v1 = x[off + t + 256], v2 = x[off + t + 512];
    float mean = block_sum_256(v0 + v1 + v2) * (1.f / 768.f);
    float d0 = v0 - mean, d1 = v1 - mean, d2 = v2 - mean;
    float var = block_sum_256(d0*d0 + d1*d1 + d2*d2) * (1.f / 768.f);
    float rstd = rsqrtf(var + 1e-6f);
    #pragma unroll
    for (int g = 0; g < 3; ++g) {
        int cx = t + g * 256;
        float dv = (g == 0) ? d0 : (g == 1) ? d1 : d2;
        float yv = dv * rstd * w[cx] + b[cx];
        y[off + cx] = yv;
        __nv_bfloat16 h, l;
        split2(yv, h, l);
        yh[off + cx] = h; yl[off + cx] = l;
    }
}

// ---------------- causal conv (K=4) + SiLU -> fp32 + hi/lo split ----------------
__global__ __launch_bounds__(256) void conv_kernel(const float* __restrict__ cw,
                                                   const float* __restrict__ cb)
{
    size_t idx = (size_t)blockIdx.x * 256 + threadIdx.x;
    int c  = (int)(idx % UP);
    int sr = (int)(idx / UP);
    int s  = sr & (SEQ - 1);
    float acc = cb[0];
    #pragma unroll
    for (int j = 0; j < KER; j++) {
        int sp = s - (KER - 1) + j;
        if (sp >= 0) acc = fmaf(cw[j], g_xt[(size_t)(sr - (KER - 1) + j) * UP + c], acc);
    }
    float v = acc * sigmoidf_(acc);
    g_xc[idx] = v;
    __nv_bfloat16 h, l;
    split2(v, h, l);
    g_xc_h[idx] = h; g_xc_l[idx] = l;
}

// ---------------- phase A: per-chunk gates + C/n contributions (R0-identical) ----------------
__global__ __launch_bounds__(256) void chunk_state_kernel()
{
    extern __shared__ float sm[];
    float* ks  = sm;
    float* vs  = ks + CS*HD;
    float* wc  = vs + CS*HD;
    float* lfs = wc + 64;
    float* igs = lfs + 64;
    float* lgs = igs + 64;

    int chunk = blockIdx.x;
    int c  = chunk & 63;
    int bh = chunk >> 6;
    int h  = bh & 7;
    int b  = bh >> 3;
    int tid = threadIdx.x;
    size_t row0 = (size_t)(b*SEQ + c*CS) * FUSED;

    if (tid < CS) {
        const float* pr = g_proj + row0 + (size_t)tid * FUSED;
        float ip = 15.f * tanhf(pr[h]      * (1.f/15.f));
        float fp = 15.f * tanhf(pr[NH + h] * (1.f/15.f));
        float mx = fmaxf(ip, fp);
        igs[tid] = expf(ip - mx);
        lgs[tid] = logf(expf(fp - mx) + 1e-8f);
    }
    __syncthreads();
    if (tid == 0) {
        float run = 0.f;
        for (int l = 0; l < CS; l++) { run += lgs[l]; lfs[l] = run; }
    }
    __syncthreads();
    if (tid < CS) wc[tid] = expf(lfs[tid] - lfs[CS-1]) * igs[tid];

    const float rs = 1.f / sqrtf((float)HD);
    for (int idx = tid; idx < CS*HD; idx += 256) {
        int l = idx / HD, d = idx % HD;
        const float* pr = g_proj + row0 + (size_t)l * FUSED;
        int col = h * HD + d;
        ks[idx] = pr[K_OFF + col] * rs;
        vs[idx] = pr[V_OFF + col];
    }
    __syncthreads();

    float* Co = g_C + (size_t)chunk * (HD*HD);
    for (int idx = tid; idx < HD*HD; idx += 256) {
        int d = idx / HD, e = idx - d*HD;
        float acc = 0.f;
        #pragma unroll 16
        for (int l = 0; l < CS; l++) acc = fmaf(wc[l] * vs[l*HD + d], ks[l*HD + e], acc);
        Co[idx] = acc;
    }
    if (tid < HD) {
        float acc = 0.f;
        for (int l = 0; l < CS; l++) acc = fmaf(wc[l], ks[l*HD + tid], acc);
        g_n[(size_t)chunk*HD + tid] = acc;
    }
    if (tid < CS) { g_lf[chunk*CS + tid] = lfs[tid]; g_ig[chunk*CS + tid] = igs[tid]; }
}

// ---------------- phase B: exclusive scan over chunks (R0-identical serial) ----------------
__global__ __launch_bounds__(256) void chunk_scan_kernel()
{
    int bh = blockIdx.x;     // 0..15
    int tid = threadIdx.x;
    for (int e = tid; e < HD*HD; e += 256) {
        float run = 0.f;
        for (int c = 0; c < NC; c++) {
            size_t idx = ((size_t)(bh*NC + c)) * (HD*HD) + e;
            float t = g_C[idx]; g_C[idx] = run; run += t;
        }
    }
    for (int e = tid; e < HD; e += 256) {
        float run = 0.f;
        for (int c = 0; c < NC; c++) {
            size_t idx = ((size_t)(bh*NC + c)) * HD + e;
            float t = g_n[idx]; g_n[idx] = run; run += t;
        }
    }
}

// ---------------- phase C: intra-chunk attention + state readout (R0-identical) ----------------
__global__ __launch_bounds__(256) void chunk_out_kernel()
{
    extern __shared__ float sm[];
    float* qs   = sm;
    float* ks   = qs  + CS*HD;
    float* vs   = ks  + CS*HD;
    float* Cs   = vs  + CS*HD;
    float* Ss   = Cs  + HD*HD;
    float* Ws   = Ss  + CS*CS;
    float* lfs  = Ws  + CS*CS;
    float* igs  = lfs + CS;
    float* nin  = igs + CS;
    float* dprt = nin + HD;

    int chunk = blockIdx.x;
    int c  = chunk & 63;
    int bh = chunk >> 6;
    int h  = bh & 7;
    int b  = bh >> 3;
    int tid = threadIdx.x;
    size_t row0 = (size_t)(b*SEQ + c*CS) * FUSED;
    const float rs = 1.f / sqrtf((float)HD);

    for (int idx = tid; idx < CS*HD; idx += 256) {
        int l = idx / HD, d = idx % HD;
        const float* pr = g_proj + row0 + (size_t)l * FUSED;
        int col = h * HD + d;
        qs[idx] = pr[Q_OFF + col];
        ks[idx] = pr[K_OFF + col] * rs;
        vs[idx] = pr[V_OFF + col];
    }
    for (int idx = tid; idx < HD*HD; idx += 256) Cs[idx] = g_C[(size_t)chunk*(HD*HD) + idx];
    if (tid < CS) { lfs[tid] = g_lf[chunk*CS + tid]; igs[tid] = g_ig[chunk*CS + tid]; }
    if (tid < HD) nin[tid] = g_n[(size_t)chunk*HD + tid];
    __syncthreads();

    for (int idx = tid; idx < CS*CS; idx += 256) {
        int i = idx >> 6, j = idx & 63;
        const float* qi = qs + i*HD;
        const float* kj = ks + j*HD;
        float acc = 0.f;
        #pragma unroll 16
        for (int d = 0; d < HD; d++) acc = fmaf(qi[d], kj[d], acc);
        Ss[idx] = acc;
    }
    __syncthreads();

    if (tid < CS) {
        int i = tid;
        float m = -1e30f;
        for (int j = 0; j < i; j++) m = fmaxf(m, Ss[i*CS + j]);
        float ssum = 0.f;
        for (int j = 0; j < i; j++) { float p = expf(Ss[i*CS + j] - m); Ss[i*CS + j] = p; ssum += p; }
        float inv = (i > 0) ? 1.f / ssum : 0.f;
        float lfi = lfs[i];
        for (int j = 0; j < CS; j++) {
            if (j < i) {
                float wv = igs[j] * expf(lfi - lfs[j]);
                Ws[i*CS + j] = wv;
                Ss[i*CS + j] = Ss[i*CS + j] * inv * wv;
            } else {
                Ws[i*CS + j] = 0.f;
                Ss[i*CS + j] = 0.f;
            }
        }
    }
    __syncthreads();

    {
        int i = tid >> 2, part = tid & 3;
        float hacc[24];
        float nq = 0.f;
        const float* qrow = qs + i*HD;
        const float* aw = Ss + i*CS;
        const float* wr = Ws + i*CS;
        #pragma unroll 4
        for (int dd = 0; dd < 24; dd++) {
            int d = part*24 + dd;
            float hi = 0.f, ni = 0.f;
            #pragma unroll 8
            for (int j = 0; j < CS; j++) {
                hi = fmaf(aw[j], vs[j*HD + d], hi);
                ni = fmaf(wr[j], ks[j*HD + d], ni);
            }
            float h0 = 0.f;
            const float* crow = Cs + d*HD;
            #pragma unroll 8
            for (int e = 0; e < HD; e++) h0 = fmaf(crow[e], qrow[e], h0);
            hacc[dd] = h0 + hi;
            nq = fmaf(ni + nin[d], qrow[d], nq);
        }
        dprt[tid] = nq;
        __syncthreads();
        float denom = fmaxf(dprt[i*4+0] + dprt[i*4+1] + dprt[i*4+2] + dprt[i*4+3], 1.f);
        float invd = 1.f / denom;
        size_t orow = (size_t)(b*SEQ + c*CS + i) * HID + h*HD + part*24;
        for (int dd = 0; dd < 24; dd++) g_h[orow + dd] = hacc[dd] * invd;
    }
}

// ---------------- fused epilogue: u = (LN(o*h)+skip)*silu(r_t) -> hi/lo split ----------------
__global__ __launch_bounds__(256) void post_kernel(const float* __restrict__ lw,
                                                   const float* __restrict__ lb)
{
    size_t off = (size_t)blockIdx.x * HID;
    int t = threadIdx.x;
    float v0 = g_o[off+t      ] * g_h[off+t      ];
    float v1 = g_o[off+t + 256] * g_h[off+t + 256];
    float v2 = g_o[off+t + 512] * g_h[off+t + 512];
    float mean = block_sum_256(v0 + v1 + v2) * (1.f / 768.f);
    float d0 = v0 - mean, d1 = v1 - mean, d2 = v2 - mean;
    float var = block_sum_256(d0*d0 + d1*d1 + d2*d2) * (1.f / 768.f);
    float rstd = rsqrtf(var + 1e-6f);
    #pragma unroll
    for (int g = 0; g < 3; ++g) {
        int cx = t + g * 256;
        float dv = (g == 0) ? d0 : (g == 1) ? d1 : d2;
        float y = dv * rstd * lw[cx] + lb[cx] + g_skip[off + cx];
        float r = g_rt[off + cx];
        float u = y * (r * sigmoidf_(r));
        __nv_bfloat16 h, l;
        split2(u, h, l);
        g_u_h[off + cx] = h; g_u_l[off + cx] = l;
    }
}

// ---------------- launch ----------------
extern "C" void kernel_launch(void* const* d_in, const int* in_sizes, int n_in,
                              void* d_out, int out_size)
{
    (void)in_sizes; (void)n_in; (void)out_size;
    const float* x        = (const float*)d_in[0];
    const float* ln_in_w  = (const float*)d_in[1];
    const float* ln_in_b  = (const float*)d_in[2];
    const float* ln_hid_w = (const float*)d_in[3];
    const float* ln_hid_b = (const float*)d_in[4];
    const float* up_l_w   = (const float*)d_in[5];
    const float* up_l_b   = (const float*)d_in[6];
    const float* up_r_w   = (const float*)d_in[7];
    const float* up_r_b   = (const float*)d_in[8];
    const float* down_w   = (const float*)d_in[9];
    const float* down_b   = (const float*)d_in[10];
    const float* conv_w   = (const float*)d_in[11];
    const float* conv_b   = (const float*)d_in[12];
    const float* skip_w   = (const float*)d_in[13];
    const float* skip_b   = (const float*)d_in[14];
    const float* fused_w  = (const float*)d_in[15];
    const float* fused_b  = (const float*)d_in[16];
    const float* wo_w     = (const float*)d_in[17];
    const float* wo_b     = (const float*)d_in[18];
    float* out = (float*)d_out;

    float *p_xn, *p_xt, *p_xc, *p_rt, *p_skip, *p_proj, *p_o;
    cudaGetSymbolAddress((void**)&p_xn,   g_xn);
    cudaGetSymbolAddress((void**)&p_xt,   g_xt);
    cudaGetSymbolAddress((void**)&p_xc,   g_xc);
    cudaGetSymbolAddress((void**)&p_rt,   g_rt);
    cudaGetSymbolAddress((void**)&p_skip, g_skip);
    cudaGetSymbolAddress((void**)&p_proj, g_proj);
    cudaGetSymbolAddress((void**)&p_o,    g_o);

    __nv_bfloat16 *xn_h,*xn_l, *xt_h,*xt_l, *xc_h,*xc_l, *u_h,*u_l;
    cudaGetSymbolAddress((void**)&xn_h, g_xn_h); cudaGetSymbolAddress((void**)&xn_l, g_xn_l);
    cudaGetSymbolAddress((void**)&xt_h, g_xt_h); cudaGetSymbolAddress((void**)&xt_l, g_xt_l);
    cudaGetSymbolAddress((void**)&xc_h, g_xc_h); cudaGetSymbolAddress((void**)&xc_l, g_xc_l);
    cudaGetSymbolAddress((void**)&u_h,  g_u_h);  cudaGetSymbolAddress((void**)&u_l,  g_u_l);

    __nv_bfloat16 *wur_h,*wur_l, *wsk_h,*wsk_l, *wwo_h,*wwo_l, *wdn_h,*wdn_l;
    cudaGetSymbolAddress((void**)&wur_h, g_wur_h); cudaGetSymbolAddress((void**)&wur_l, g_wur_l);
    cudaGetSymbolAddress((void**)&wsk_h, g_wsk_h); cudaGetSymbolAddress((void**)&wsk_l, g_wsk_l);
    cudaGetSymbolAddress((void**)&wwo_h, g_wwo_h); cudaGetSymbolAddress((void**)&wwo_l, g_wwo_l);
    cudaGetSymbolAddress((void**)&wdn_h, g_wdn_h); cudaGetSymbolAddress((void**)&wdn_l, g_wdn_l);

    const int SMEM_A = (2*CS*HD + 4*64) * 4;
    const int SMEM_C = (3*CS*HD + HD*HD + 2*CS*CS + 2*CS + HD + 256) * 4;
    cudaFuncSetAttribute(chunk_state_kernel, cudaFuncAttributeMaxDynamicSharedMemorySize, SMEM_A);
    cudaFuncSetAttribute(chunk_out_kernel,   cudaFuncAttributeMaxDynamicSharedMemorySize, SMEM_C);
    cudaFuncSetAttribute(gemm2_kernel,       cudaFuncAttributeMaxDynamicSharedMemorySize, G2_SMEM);

    // 0) weight transpose + hi/lo split for the four mma GEMMs
    wsplit_kernel<<<(HID*D_IN)/256, 256>>>(up_r_w, wur_h, wur_l, D_IN, HID);
    wsplit_kernel<<<(HID*UP)/256, 256>>>(skip_w, wsk_h, wsk_l, UP, HID);
    wsplit_kernel<<<(HID*UP)/256, 256>>>(wo_w, wwo_h, wwo_l, UP, HID);
    wsplit_kernel<<<(D_IN*HID)/256, 256>>>(down_w, wdn_h, wdn_l, HID, D_IN);

    // 1) input LN -> xn fp32 + split
    ln_split_kernel<<<TOK, 256>>>(x, ln_in_w, ln_in_b, p_xn, xn_h, xn_l);
    // 2) x_t = xn @ up_l  (fp32 sgemm; writes xt fp32 + split for wo)
    sgemm_kernel<<<dim3(UP/128, TOK/128), 256>>>(
        p_xn, up_l_w, up_l_b, nullptr, p_xt, xt_h, xt_l, TOK, UP, D_IN, 0);
    // 3) r_t = xn @ up_r  (fresh mma)
    gemm2_kernel<<<dim3(HID/128, TOK/128), 256, G2_SMEM>>>(
        xn_h, xn_l, wur_h, wur_l, up_r_b, nullptr, p_rt, TOK, HID, D_IN, 0);
    // 4) causal conv + silu -> xc fp32 + split
    conv_kernel<<<(TOK*UP)/256, 256>>>(conv_w, conv_b);
    // 5) x_skip = xc @ skip_w  (fresh mma)
    gemm2_kernel<<<dim3(HID/128, TOK/128), 256, G2_SMEM>>>(
        xc_h, xc_l, wsk_h, wsk_l, skip_b, nullptr, p_skip, TOK, HID, UP, 0);
    // 6) proj = xc @ fused_w  (fp32 sgemm; exact gates + q/k/v)
    sgemm_kernel<<<dim3((FUSED+127)/128, TOK/128), 256>>>(
        p_xc, fused_w, fused_b, nullptr, p_proj, nullptr, nullptr, TOK, FUSED, UP, 0);
    // 7) o = sigmoid(xt @ wo_w)  (fresh mma)
    gemm2_kernel<<<dim3(HID/128, TOK/128), 256, G2_SMEM>>>(
        xt_h, xt_l, wwo_h, wwo_l, wo_b, nullptr, p_o, TOK, HID, UP, 1);
    // 8-10) chunked mLSTM attention (R0-identical)
    chunk_state_kernel<<<NCHUNK, 256, SMEM_A>>>();
    chunk_scan_kernel<<<NB*NH, 256>>>();
    chunk_out_kernel<<<NCHUNK, 256, SMEM_C>>>();
    // 11) u = (LN(o*h)+skip)*silu(r_t) -> u split
    post_kernel<<<TOK, 256>>>(ln_hid_w, ln_hid_b);
    // 12) out = u @ down_w + down_b + x  (fresh mma)
    gemm2_kernel<<<dim3(D_IN/128, TOK/128), 256, G2_SMEM>>>(
        u_h, u_l, wdn_h, wdn_l, down_b, x, out, TOK, D_IN, HID, 2);
}